// round 6
// baseline (speedup 1.0000x reference)
#include <cuda_runtime.h>
#include <math.h>

#define IMG    512
#define NPIX   (IMG*IMG)
#define NB     4
#define NO     6
#define NL     4
#define TILE_C 64
#define TILE_R 32
#define TSC    71     // centered cols extent + stride (odd -> conflict-free)
#define TSR    39     // centered rows extent (TILE_R + 7)
#define XC     78     // raw tile cols
#define XRW    46     // raw tile rows (TILE_R + 14)
#define XS2    79     // raw tile stride (odd)
#define HS     65     // H box-buffer stride (odd), TSR rows x 64 cols used
#define EPS    1e-20f
#define NT     512
#define GX     8
#define GY     16
#define NCTA   (GX*GY*NB)   // 512

// sizes in floats
#define SZ_BC   (TSR*TSC)      // 2769
#define SZ_X    (XRW*XS2)      // 3634
#define SZ_HM   (XRW*TSC)      // 3266
#define SZ_HB   (TSR*HS)       // 2535
#define R_FLOATS (5*SZ_HB)     // 12675 >= SZ_X+SZ_HM (6900)
#define SMEM_FLOATS (NL*SZ_BC + SZ_BC + R_FLOATS)   // 26520 -> 106,080 B

__device__ float d_partial[NB*NO*GX*GY];
__device__ unsigned int d_count = 0;

// ---- load raw 46x78 tile (zero outside image) ----
__device__ __forceinline__ void load_tile(const float* __restrict__ src, float* __restrict__ X,
                                          int tx0, int ty0, int tid) {
    for (int idx = tid; idx < XRW*XC; idx += NT) {
        int r = idx / XC, c = idx % XC;
        int gr = ty0 + r - 6, gc = tx0 + c - 6;
        float v = 0.f;
        if ((unsigned)gr < (unsigned)IMG && (unsigned)gc < (unsigned)IMG)
            v = __ldg(src + gr*IMG + gc);
        X[r*XS2 + c] = v;
    }
}

// ---- Hm[r][c] = sum_{d=0..7} X[r][c+d], r<46, c<71 (reg-staged) ----
__device__ __forceinline__ void hmean(const float* __restrict__ X, float* __restrict__ Hm, int tid) {
    for (int idx = tid; idx < XRW*8; idx += NT) {
        int r = idx % XRW, q = idx / XRW;
        int c0 = q * 9;
        int cnt = (q == 7) ? 8 : 9;
        const float* xr = X + r*XS2 + c0;
        float w[16];
        #pragma unroll
        for (int d = 0; d < 16; d++) w[d] = xr[d];     // col <= 78 < stride 79
        float s = w[0]+w[1]+w[2]+w[3]+w[4]+w[5]+w[6]+w[7];
        float* hr = Hm + r*TSC + c0;
        hr[0] = s;
        #pragma unroll
        for (int k = 1; k < 9; k++)
            if (k < cnt) { s += w[k+7] - w[k-1]; hr[k] = s; }
    }
}

// ---- OUT[r][c] = inside ? X[r+3][c+3] - boxmean : 0,  r<39, c<71 ----
__device__ __forceinline__ void centered(const float* __restrict__ X, const float* __restrict__ Hm,
                                         float* __restrict__ OUT, int tx0, int ty0, int tid) {
    for (int idx = tid; idx < TSC*5; idx += NT) {
        int c = idx % TSC, q = idx / TSC;     // q in 0..4, row chunks of 8
        int r0 = q * 8;
        int cnt = min(8, TSR - r0);           // 8,8,8,8,7
        float h[15];
        #pragma unroll
        for (int d = 0; d < 15; d++) h[d] = Hm[min(r0 + d, XRW-1)*TSC + c];
        float xv[8];
        #pragma unroll
        for (int k = 0; k < 8; k++) xv[k] = X[(r0 + k + 3)*XS2 + (c + 3)];
        float s = h[0]+h[1]+h[2]+h[3]+h[4]+h[5]+h[6]+h[7];
        int gc = tx0 + c - 3;
        bool cin = (unsigned)gc < (unsigned)IMG;
        #pragma unroll
        for (int k = 0; k < 8; k++) {
            if (k < cnt) {
                int r = r0 + k;
                int gr = ty0 + r - 3;
                float v = 0.f;
                if (cin && (unsigned)gr < (unsigned)IMG) v = xv[k] - s * (1.f/64.f);
                OUT[r*TSC + c] = v;
                if (k + 1 < cnt) s += h[k+8] - h[k];
            }
        }
    }
}

// ---- 4 vertical window sums of Hb at column cl, row group g ----
__device__ __forceinline__ void vsum4(const float* __restrict__ Hb, int g, int cl, float* out) {
    float ps[12];
    ps[0] = 0.f;
    #pragma unroll
    for (int k = 0; k < 11; k++) ps[k+1] = ps[k] + Hb[(g*4 + k)*HS + cl];
    #pragma unroll
    for (int k = 0; k < 4; k++) out[k] = ps[k+8] - ps[k];
}

// =========================================================================
// fused: one CTA per (batch, 64x32 tile), 512 threads, 2 CTAs/SM resident.
// =========================================================================
__global__ void __launch_bounds__(NT, 2)
fused_kernel(const float* __restrict__ outs, const float* __restrict__ labs,
             float* __restrict__ out, int out_size) {
    extern __shared__ float sm[];
    float* BC = sm;                  // NL * 2769
    float* AC = BC + NL*SZ_BC;       // 2769 (head doubles as reduction scratch)
    float* R  = AC + SZ_BC;          // 12675: prep {X, Hm} / corr {H0..H4}
    float* X  = R;                   // 3634, stride 79
    float* Hm = R + SZ_X;            // 3266, stride 71
    __shared__ unsigned int s_flag;
    __shared__ float s_vals[NB*NO];

    int tx0 = blockIdx.x * TILE_C, ty0 = blockIdx.y * TILE_R;
    int b = blockIdx.z;
    int tid = threadIdx.x;
    int cl = tid & 63, g = tid >> 6;      // pixel column / row-group (g in 0..7, 4 rows)
    int lane = tid & 31, wid = tid >> 5;

    // ---------------- phase 1: labels -> BC[l], rsjj regs ----------------
    for (int l = 0; l < NL; l++) {
        load_tile(labs + (size_t)(b*NL + l)*NPIX, X, tx0, ty0, tid);
        __syncthreads();
        hmean(X, Hm, tid);
        __syncthreads();
        centered(X, Hm, BC + l*SZ_BC, tx0, ty0, tid);
        __syncthreads();   // BC[l] ready; X/Hm retire before next load
    }

    // balanced phase: box-row sums of bc_l^2, items = 4 labels x 39 rows x 8 chunks
    for (int idx = tid; idx < NL*TSR*8; idx += NT) {
        int l = idx / (TSR*8), rem = idx % (TSR*8);
        int r = rem % TSR, q = rem / TSR;
        int c0 = q * 8;
        const float* br = BC + l*SZ_BC + r*TSC + c0;
        float w[15];
        #pragma unroll
        for (int d = 0; d < 15; d++) { float v = br[d]; w[d] = v*v; }
        float s = w[0]+w[1]+w[2]+w[3]+w[4]+w[5]+w[6]+w[7];
        float* hr = R + l*SZ_HB + r*HS + c0;
        hr[0] = s;
        #pragma unroll
        for (int k = 1; k < 8; k++) { s += w[k+7] - w[k-1]; hr[k] = s; }
    }
    __syncthreads();

    float rsjjR[NL][4];
    #pragma unroll
    for (int l = 0; l < NL; l++) {
        float v4[4];
        vsum4(R + l*SZ_HB, g, cl, v4);
        #pragma unroll
        for (int k = 0; k < 4; k++) rsjjR[l][k] = rsqrtf(fmaxf(v4[k], EPS));
    }
    __syncthreads();   // rsjj in regs; R free for phase 2

    // ---------------- phase 2: outputs ----------------
    for (int o = 0; o < NO; o++) {
        load_tile(outs + (size_t)(b*NO + o)*NPIX, X, tx0, ty0, tid);
        __syncthreads();
        hmean(X, Hm, tid);
        __syncthreads();
        centered(X, Hm, AC, tx0, ty0, tid);
        __syncthreads();   // AC ready; X/Hm dead -> R hosts H0..H4

        // balanced phase: j=0 -> ac*ac, j=1..4 -> ac*bc_{j-1}; 1560 items
        for (int idx = tid; idx < 5*TSR*8; idx += NT) {
            int j = idx / (TSR*8), rem = idx % (TSR*8);
            int r = rem % TSR, q = rem / TSR;
            int c0 = q * 8;
            const float* ar = AC + r*TSC + c0;
            const float* br = (j == 0) ? ar : (BC + (j-1)*SZ_BC + r*TSC + c0);
            float w[15];
            #pragma unroll
            for (int d = 0; d < 15; d++) w[d] = ar[d] * br[d];
            float s = w[0]+w[1]+w[2]+w[3]+w[4]+w[5]+w[6]+w[7];
            float* hr = R + j*SZ_HB + r*HS + c0;
            hr[0] = s;
            #pragma unroll
            for (int k = 1; k < 8; k++) { s += w[k+7] - w[k-1]; hr[k] = s; }
        }
        __syncthreads();

        float rsii[4];
        {
            float v4[4];
            vsum4(R, g, cl, v4);
            #pragma unroll
            for (int k = 0; k < 4; k++) rsii[k] = rsqrtf(fmaxf(v4[k], EPS));
        }

        float maxcc[4];
        #pragma unroll
        for (int k = 0; k < 4; k++) maxcc[k] = -1.0f;

        #pragma unroll
        for (int l = 0; l < NL; l++) {
            float sij4[4];
            vsum4(R + (l+1)*SZ_HB, g, cl, sij4);
            #pragma unroll
            for (int k = 0; k < 4; k++) {
                float cc = sij4[k] * (rsii[k] * rsjjR[l][k]);
                maxcc[k] = fmaxf(maxcc[k], cc);
            }
        }

        float local = 0.f;
        #pragma unroll
        for (int k = 0; k < 4; k++) local += 1.0f - fminf(1.0f, maxcc[k]);
        #pragma unroll
        for (int off = 16; off > 0; off >>= 1)
            local += __shfl_down_sync(0xFFFFFFFFu, local, off);
        if (lane == 0) AC[wid] = local;   // AC hprod-readers retired at last sync
        __syncthreads();
        if (tid == 0) {
            float s = 0.f;
            #pragma unroll
            for (int w2 = 0; w2 < 16; w2++) s += AC[w2];
            d_partial[(b*NO + o)*(GX*GY) + blockIdx.y*GX + blockIdx.x] = s;
        }
        // next load_tile writes R (disjoint from AC scratch); tid0 rejoins at
        // the post-load barrier before the next centered overwrites AC.
    }

    // ---------------- in-kernel finalize (last CTA, fixed-order sums) ------
    if (tid == 0) {
        __threadfence();
        unsigned int v = atomicAdd(&d_count, 1u);
        s_flag = (v == NCTA - 1) ? 1u : 0u;
    }
    __syncthreads();
    if (s_flag) {
        __threadfence();   // acquire: all CTAs' d_partial visible
        if (tid < NB*NO) {
            float s = 0.f;
            for (int i = 0; i < GX*GY; i++) s += d_partial[tid*(GX*GY) + i];
            float m = s * (1.0f / (float)NPIX);
            s_vals[tid] = m;
            if (1 + tid < out_size) out[1 + tid] = m;
        }
        __syncthreads();
        if (tid == 0) {
            float s = 0.f;
            #pragma unroll
            for (int i = 0; i < NB*NO; i++) s += s_vals[i];
            if (out_size > 0) out[0] = s / (float)(NB*NO);
            d_count = 0;   // reset for next graph replay
        }
    }
}

extern "C" void kernel_launch(void* const* d_in, const int* in_sizes, int n_in,
                              void* d_out, int out_size) {
    const float* outs = (const float*)d_in[0];
    const float* labs = (const float*)d_in[1];
    if (n_in >= 2 && in_sizes[0] < in_sizes[1]) {  // defensive: outputs is larger
        const float* tmp = outs; outs = labs; labs = tmp;
    }

    const int SMEM = SMEM_FLOATS * (int)sizeof(float);   // 106,080 B
    cudaFuncSetAttribute(fused_kernel, cudaFuncAttributeMaxDynamicSharedMemorySize, SMEM);
    fused_kernel<<<dim3(GX, GY, NB), NT, SMEM>>>(outs, labs, (float*)d_out, out_size);
}

// round 7
// speedup vs baseline: 1.2190x; 1.2190x over previous
#include <cuda_runtime.h>
#include <math.h>

#define IMG   512
#define NPIX  (IMG*IMG)
#define NB    4
#define NO    6
#define NL    4
#define TILE  64
#define TS    71      // centered extent (rows & cols)
#define BCS   76      // BC/AC stride: 76 mod 32 = 12 -> conflict-free float4 rows
#define XR    78      // raw tile rows/cols
#define XS2   84      // raw tile stride: 84 mod 32 = 20 -> conflict-free float4
#define HMS   76      // Hm stride
#define HS    68      // H box-buffer stride: 68 mod 32 = 4 -> cf float4, 16B aligned
#define EPS   1e-20f
#define NT    1024
#define NCTA  (8*8*NB)   // 256

// sizes in floats (all multiples of 4 -> float4 alignment preserved)
#define SZ_BC   (TS*BCS)       // 5396
#define SZ_X    (XR*XS2)       // 6552
#define SZ_HM   (XR*HMS)       // 5928
#define SZ_HB   (TS*HS)        // 4828
#define R_FLOATS (5*SZ_HB)     // 24140 >= SZ_X+SZ_HM (12480)
#define SMEM_FLOATS (NL*SZ_BC + SZ_BC + R_FLOATS)   // 51120 -> 204,480 B

__device__ float d_partial[NB*NO*64];
__device__ unsigned int d_count = 0;

// ---- load raw 78x78 tile (zero outside image) ----
__device__ __forceinline__ void load_tile(const float* __restrict__ src, float* __restrict__ X,
                                          int tx0, int ty0, int tid) {
    for (int idx = tid; idx < XR*XR; idx += NT) {
        int r = idx / XR, c = idx % XR;
        int gr = ty0 + r - 6, gc = tx0 + c - 6;
        float v = 0.f;
        if ((unsigned)gr < (unsigned)IMG && (unsigned)gc < (unsigned)IMG)
            v = __ldg(src + gr*IMG + gc);
        X[r*XS2 + c] = v;
    }
}

// ---- Hm[r][c] = sum_{d=0..7} X[r][c+d], r<78, c<71 ; float4 in/out ----
// Uniform 8-output chunks; chunk q=8 writes cols 64..71 (col 71 = stride padding).
__device__ __forceinline__ void hmean(const float* __restrict__ X, float* __restrict__ Hm, int tid) {
    for (int idx = tid; idx < XR*9; idx += NT) {
        int r = idx % XR, q = idx / XR;
        int c0 = q * 8;                                   // 0..64
        const float4* xp = (const float4*)(X + r*XS2 + c0);   // cols c0..c0+15 (<=79 < 84)
        float4 v0 = xp[0], v1 = xp[1], v2 = xp[2], v3 = xp[3];
        float w[16] = {v0.x,v0.y,v0.z,v0.w, v1.x,v1.y,v1.z,v1.w,
                       v2.x,v2.y,v2.z,v2.w, v3.x,v3.y,v3.z,v3.w};
        float o[8];
        float s = w[0]+w[1]+w[2]+w[3]+w[4]+w[5]+w[6]+w[7];
        o[0] = s;
        #pragma unroll
        for (int k = 1; k < 8; k++) { s += w[k+7] - w[k-1]; o[k] = s; }
        float4* hp = (float4*)(Hm + r*HMS + c0);
        hp[0] = make_float4(o[0],o[1],o[2],o[3]);
        hp[1] = make_float4(o[4],o[5],o[6],o[7]);
    }
}

// ---- OUT[r][c] = inside ? X[r+3][c+3] - boxmean : 0, r,c<71 (column items) ----
__device__ __forceinline__ void centered(const float* __restrict__ X, const float* __restrict__ Hm,
                                         float* __restrict__ OUT, int tx0, int ty0, int tid) {
    for (int idx = tid; idx < TS*9; idx += NT) {
        int c = idx % TS, q = idx / TS;                   // q 0..8, row chunks of 8
        int r0 = q * 8;
        int cnt = min(8, TS - r0);                        // last chunk = 7
        float h[15];
        #pragma unroll
        for (int d = 0; d < 15; d++) h[d] = Hm[min(r0 + d, XR-1)*HMS + c];
        float xv[8];
        #pragma unroll
        for (int k = 0; k < 8; k++) xv[k] = X[(r0 + k + 3)*XS2 + (c + 3)];  // row<=74<78
        float s = h[0]+h[1]+h[2]+h[3]+h[4]+h[5]+h[6]+h[7];
        int gc = tx0 + c - 3;
        bool cin = (unsigned)gc < (unsigned)IMG;
        #pragma unroll
        for (int k = 0; k < 8; k++) {
            if (k < cnt) {
                int r = r0 + k;
                int gr = ty0 + r - 3;
                float v = 0.f;
                if (cin && (unsigned)gr < (unsigned)IMG) v = xv[k] - s * (1.f/64.f);
                OUT[r*BCS + c] = v;
                if (k + 1 < cnt) s += h[k+8] - h[k];
            }
        }
    }
}

// ---- row window-sum of w[0..14] -> 8 outputs, float4-stored ----
__device__ __forceinline__ void prefix_store(const float* w, float* __restrict__ hr) {
    float o[8];
    float s = w[0]+w[1]+w[2]+w[3]+w[4]+w[5]+w[6]+w[7];
    o[0] = s;
    #pragma unroll
    for (int k = 1; k < 8; k++) { s += w[k+7] - w[k-1]; o[k] = s; }
    float4* hp = (float4*)hr;
    hp[0] = make_float4(o[0],o[1],o[2],o[3]);
    hp[1] = make_float4(o[4],o[5],o[6],o[7]);
}

// ---- 4 vertical window sums of Hb at column cl, row group g ----
__device__ __forceinline__ void vsum4(const float* __restrict__ Hb, int g, int cl, float* out) {
    float ps[12];
    ps[0] = 0.f;
    #pragma unroll
    for (int k = 0; k < 11; k++) ps[k+1] = ps[k] + Hb[(g*4 + k)*HS + cl];
    #pragma unroll
    for (int k = 0; k < 4; k++) out[k] = ps[k+8] - ps[k];
}

// =========================================================================
// fused: one CTA per (batch, 64x64 tile), 1024 threads, finalize in-kernel.
// =========================================================================
__global__ void __launch_bounds__(NT, 1)
fused_kernel(const float* __restrict__ outs, const float* __restrict__ labs,
             float* __restrict__ out, int out_size) {
    extern __shared__ float sm[];
    float* BC = sm;                  // NL * 5396
    float* AC = BC + NL*SZ_BC;       // 5396 (head doubles as reduction scratch)
    float* R  = AC + SZ_BC;          // 24140: prep {X, Hm} / corr {H0..H4}
    float* X  = R;                   // 6552, stride 84
    float* Hm = R + SZ_X;            // 5928, stride 76
    __shared__ unsigned int s_flag;
    __shared__ float s_vals[NB*NO];

    int tx0 = blockIdx.x * TILE, ty0 = blockIdx.y * TILE;
    int b = blockIdx.z;
    int tid = threadIdx.x;
    int cl = tid & 63, g = tid >> 6;      // pixel column / row-group (g 0..15, 4 rows)
    int lane = tid & 31, wid = tid >> 5;

    // ---------------- phase 1: labels -> BC[l], rsjj regs ----------------
    for (int l = 0; l < NL; l++) {
        load_tile(labs + (size_t)(b*NL + l)*NPIX, X, tx0, ty0, tid);
        __syncthreads();
        hmean(X, Hm, tid);
        __syncthreads();
        centered(X, Hm, BC + l*SZ_BC, tx0, ty0, tid);
        __syncthreads();   // BC[l] ready; X/Hm retire before next load
    }

    // box-row sums of bc_l^2 for all 4 labels -> R[0..3]  (568 items)
    for (int idx = tid; idx < TS*8; idx += NT) {
        int r = idx % TS, q = idx / TS;
        int c0 = q * 8;                                   // <=56; window cols <=71<76
        #pragma unroll
        for (int l = 0; l < NL; l++) {
            const float4* bp = (const float4*)(BC + l*SZ_BC + r*BCS + c0);
            float4 v0 = bp[0], v1 = bp[1], v2 = bp[2], v3 = bp[3];
            float bb[16] = {v0.x,v0.y,v0.z,v0.w, v1.x,v1.y,v1.z,v1.w,
                            v2.x,v2.y,v2.z,v2.w, v3.x,v3.y,v3.z,v3.w};
            float w[15];
            #pragma unroll
            for (int d = 0; d < 15; d++) w[d] = bb[d]*bb[d];
            prefix_store(w, R + l*SZ_HB + r*HS + c0);
        }
    }
    __syncthreads();

    float rsjjR[NL][4];
    #pragma unroll
    for (int l = 0; l < NL; l++) {
        float v4[4];
        vsum4(R + l*SZ_HB, g, cl, v4);
        #pragma unroll
        for (int k = 0; k < 4; k++) rsjjR[l][k] = rsqrtf(fmaxf(v4[k], EPS));
    }
    __syncthreads();   // rsjj in regs; R free for phase 2

    // ---------------- phase 2: outputs ----------------
    for (int o = 0; o < NO; o++) {
        load_tile(outs + (size_t)(b*NO + o)*NPIX, X, tx0, ty0, tid);
        __syncthreads();
        hmean(X, Hm, tid);
        __syncthreads();
        centered(X, Hm, AC, tx0, ty0, tid);
        __syncthreads();   // AC ready; X/Hm dead -> R hosts H0..H4

        // fused phase: ac loaded once; j=0 -> ac*ac, j=1..4 -> ac*bc_{j-1}
        for (int idx = tid; idx < TS*8; idx += NT) {
            int r = idx % TS, q = idx / TS;
            int c0 = q * 8;
            const float4* ap = (const float4*)(AC + r*BCS + c0);
            float4 a0 = ap[0], a1 = ap[1], a2 = ap[2], a3 = ap[3];
            float a[16] = {a0.x,a0.y,a0.z,a0.w, a1.x,a1.y,a1.z,a1.w,
                           a2.x,a2.y,a2.z,a2.w, a3.x,a3.y,a3.z,a3.w};
            {
                float w[15];
                #pragma unroll
                for (int d = 0; d < 15; d++) w[d] = a[d]*a[d];
                prefix_store(w, R + r*HS + c0);
            }
            #pragma unroll
            for (int l = 0; l < NL; l++) {
                const float4* bp = (const float4*)(BC + l*SZ_BC + r*BCS + c0);
                float4 v0 = bp[0], v1 = bp[1], v2 = bp[2], v3 = bp[3];
                float bb[16] = {v0.x,v0.y,v0.z,v0.w, v1.x,v1.y,v1.z,v1.w,
                                v2.x,v2.y,v2.z,v2.w, v3.x,v3.y,v3.z,v3.w};
                float w[15];
                #pragma unroll
                for (int d = 0; d < 15; d++) w[d] = a[d]*bb[d];
                prefix_store(w, R + (l+1)*SZ_HB + r*HS + c0);
            }
        }
        __syncthreads();

        float rsii[4];
        {
            float v4[4];
            vsum4(R, g, cl, v4);
            #pragma unroll
            for (int k = 0; k < 4; k++) rsii[k] = rsqrtf(fmaxf(v4[k], EPS));
        }

        float maxcc[4];
        #pragma unroll
        for (int k = 0; k < 4; k++) maxcc[k] = -1.0f;

        #pragma unroll
        for (int l = 0; l < NL; l++) {
            float sij4[4];
            vsum4(R + (l+1)*SZ_HB, g, cl, sij4);
            #pragma unroll
            for (int k = 0; k < 4; k++) {
                float cc = sij4[k] * (rsii[k] * rsjjR[l][k]);
                maxcc[k] = fmaxf(maxcc[k], cc);
            }
        }

        float local = 0.f;
        #pragma unroll
        for (int k = 0; k < 4; k++) local += 1.0f - fminf(1.0f, maxcc[k]);
        #pragma unroll
        for (int off = 16; off > 0; off >>= 1)
            local += __shfl_down_sync(0xFFFFFFFFu, local, off);
        if (lane == 0) AC[wid] = local;   // AC hprod-readers retired at last sync
        __syncthreads();
        if (tid == 0) {
            float s = 0.f;
            #pragma unroll
            for (int w2 = 0; w2 < 32; w2++) s += AC[w2];
            d_partial[(b*NO + o)*64 + blockIdx.y*8 + blockIdx.x] = s;
        }
        // next load_tile writes R (disjoint from AC scratch); tid0 rejoins at
        // the post-load barrier before the next centered overwrites AC.
    }

    // ---------------- in-kernel finalize (last CTA, fixed-order sums) ------
    if (tid == 0) {
        __threadfence();
        unsigned int v = atomicAdd(&d_count, 1u);
        s_flag = (v == NCTA - 1) ? 1u : 0u;
    }
    __syncthreads();
    if (s_flag) {
        __threadfence();   // acquire: all CTAs' d_partial visible
        if (tid < NB*NO) {
            float s = 0.f;
            for (int i = 0; i < 64; i++) s += d_partial[tid*64 + i];
            float m = s * (1.0f / (float)NPIX);
            s_vals[tid] = m;
            if (1 + tid < out_size) out[1 + tid] = m;
        }
        __syncthreads();
        if (tid == 0) {
            float s = 0.f;
            #pragma unroll
            for (int i = 0; i < NB*NO; i++) s += s_vals[i];
            if (out_size > 0) out[0] = s / (float)(NB*NO);
            d_count = 0;   // reset for next graph replay
        }
    }
}

extern "C" void kernel_launch(void* const* d_in, const int* in_sizes, int n_in,
                              void* d_out, int out_size) {
    const float* outs = (const float*)d_in[0];
    const float* labs = (const float*)d_in[1];
    if (n_in >= 2 && in_sizes[0] < in_sizes[1]) {  // defensive: outputs is larger
        const float* tmp = outs; outs = labs; labs = tmp;
    }

    const int SMEM = SMEM_FLOATS * (int)sizeof(float);   // 204,480 B
    cudaFuncSetAttribute(fused_kernel, cudaFuncAttributeMaxDynamicSharedMemorySize, SMEM);
    fused_kernel<<<dim3(8, 8, NB), NT, SMEM>>>(outs, labs, (float*)d_out, out_size);
}